// round 16
// baseline (speedup 1.0000x reference)
#include <cuda_runtime.h>
#include <cstdint>

// -------------------------------------------------------------------------
// SpecialSpmmFinal: out[n,f] = sum_{e : src[e]==n} edge_w[e,f]
// N=100000, E=3200000, F=16 fp32.
//
// Single fused kernel: coalesced-atomic scatter (4 threads/edge, 16B
// quarter-rows, x8 ILP — at the measured LTS floor ~50us) with the output
// zeroing folded in via a first-wave software barrier:
//   - blocks 0..ZBLK-1 zero the 6.4MB output, release-arrive on g_arrive
//   - ALL blocks batch their 16 input loads BEFORE spinning on the flag,
//     so zeroing hides under the load phase (manual PDL that works)
//   - counters self-reset (last block) => deterministic across replays.
// -------------------------------------------------------------------------

#define FEAT   16
#define UNROLL 8
#define ZBLK   196     // zeroing blocks
#define ZPT    8       // float4 zeroed per thread: 196*256*8 >= 400000

__device__ int g_arrive = 0;
__device__ int g_done   = 0;

__device__ __forceinline__ float4 ldg_stream(const float4* p) {
    float4 v;
    asm volatile("ld.global.nc.L1::no_allocate.v4.f32 {%0,%1,%2,%3}, [%4];"
                 : "=f"(v.x), "=f"(v.y), "=f"(v.z), "=f"(v.w) : "l"(p));
    return v;
}

__device__ __forceinline__ void red_v4(float* o, float4 v) {
    asm volatile("red.global.add.v4.f32 [%0], {%1,%2,%3,%4};"
                 :: "l"(o), "f"(v.x), "f"(v.y), "f"(v.z), "f"(v.w) : "memory");
}

// Exact version: total quarter-rows == gridDim.x * blockDim.x * UNROLL.
__global__ __launch_bounds__(256)
void spmm_fused_kernel(const int* __restrict__ src,
                       const float4* __restrict__ w,   // [E*4]
                       float* __restrict__ out,        // [N*16]
                       int n4)                         // out float4 count
{
    const int stride = gridDim.x * blockDim.x;
    const int base = blockIdx.x * blockDim.x + threadIdx.x;
    const int tid = threadIdx.x;

    int    s[UNROLL];
    float4 v[UNROLL];

    // ---- Phase 1: batch input loads (inputs untouched by zeroing) ----
    #pragma unroll
    for (int k = 0; k < UNROLL; k++) {
        int idx = base + k * stride;
        s[k] = __ldg(&src[idx >> 2]);
    }
    #pragma unroll
    for (int k = 0; k < UNROLL; k++) {
        v[k] = ldg_stream(&w[base + k * stride]);
    }

    // ---- Phase 2: first ZBLK blocks zero the output ----
    if (blockIdx.x < ZBLK) {
        const float4 z = make_float4(0.f, 0.f, 0.f, 0.f);
        int zi = (blockIdx.x * 256 + tid) * ZPT;
        #pragma unroll
        for (int k = 0; k < ZPT; k++) {
            int j = zi + k;
            if (j < n4) ((float4*)out)[j] = z;
        }
        __syncthreads();                 // block's zero stores issued
        if (tid == 0) {
            __threadfence();             // release zero stores
            atomicAdd(&g_arrive, 1);
        }
    }

    // ---- Phase 3: wait until the whole output is zeroed ----
    if (tid == 0) {
        while (*(volatile int*)&g_arrive < ZBLK) __nanosleep(64);
    }
    __syncthreads();
    __threadfence();                     // acquire zero stores

    // ---- Phase 4: coalesced vector reductions ----
    #pragma unroll
    for (int k = 0; k < UNROLL; k++) {
        int idx = base + k * stride;
        red_v4(out + (size_t)s[k] * FEAT + (idx & 3) * 4, v[k]);
    }

    // ---- Phase 5: last block resets the counters for the next replay ----
    if (tid == 0) {
        __threadfence();
        int d = atomicAdd(&g_done, 1);
        if (d == (int)gridDim.x - 1) {
            g_done   = 0;
            g_arrive = 0;
            __threadfence();
        }
    }
}

// Generic fallback (predicated) for any E; output zeroed by memsetAsync.
__global__ __launch_bounds__(256)
void spmm_scatter_gen_kernel(const int* __restrict__ src,
                             const float4* __restrict__ w,
                             float* __restrict__ out,
                             int total)
{
    const int stride = gridDim.x * blockDim.x;
    const int base = blockIdx.x * blockDim.x + threadIdx.x;

    #pragma unroll
    for (int k = 0; k < UNROLL; k++) {
        int idx = base + k * stride;
        if (idx < total) {
            int s = __ldg(&src[idx >> 2]);
            float4 v = ldg_stream(&w[idx]);
            red_v4(out + (size_t)s * FEAT + (idx & 3) * 4, v);
        }
    }
}

extern "C" void kernel_launch(void* const* d_in, const int* in_sizes, int n_in,
                              void* d_out, int out_size) {
    const int*    edge   = (const int*)d_in[0];      // [2, E], row 0 = src
    const float4* edge_w = (const float4*)d_in[1];   // [E, 16] as float4
    float*        out    = (float*)d_out;            // [N, 16] fp32

    const int E = in_sizes[0] / 2;

    const long long total = (long long)E * 4;        // quarter-rows
    const int per_blk = 256 * UNROLL;

    if (total % per_blk == 0 && total / per_blk >= ZBLK) {
        int blocks = (int)(total / per_blk);         // E=3.2M -> 6250
        int n4 = out_size / 4;
        spmm_fused_kernel<<<blocks, 256>>>(edge, edge_w, out, n4);
    } else {
        cudaMemsetAsync(out, 0, (size_t)out_size * sizeof(float));
        long long threads = (total + UNROLL - 1) / UNROLL;
        int blocks = (int)((threads + 255) / 256);
        spmm_scatter_gen_kernel<<<blocks, 256>>>(edge, edge_w, out, (int)total);
    }
}